// round 11
// baseline (speedup 1.0000x reference)
#include <cuda_runtime.h>
#include <cuda_fp16.h>
#include <math.h>
#include <stdint.h>

#define OLDV 50257
#define FINV 52257
#define EMB_D 2048
#define T_TOK 32768
#define NNUM 4096
#define KDIM 8192
#define MGEMM 4096
#define NGEMM 2048

// fp16 scratch: hidden activations and W2
__device__ __align__(128) __half g_hh[(size_t)NNUM * KDIM];    // [4096, 8192] row-major
__device__ __align__(128) __half g_w2h[(size_t)KDIM * NGEMM];  // [8192, 2048] row-major

// ---------------------------------------------------------------------------
// helpers
// ---------------------------------------------------------------------------
__device__ __forceinline__ uint32_t s2u(const void* p) {
    uint32_t a;
    asm("{ .reg .u64 t; cvta.to.shared.u64 t, %1; cvt.u32.u64 %0, t; }"
        : "=r"(a) : "l"(p));
    return a;
}
__device__ __forceinline__ void ldsm_x4(uint32_t* r, uint32_t addr) {
    asm volatile("ldmatrix.sync.aligned.m8n8.x4.shared.b16 {%0,%1,%2,%3}, [%4];"
                 : "=r"(r[0]), "=r"(r[1]), "=r"(r[2]), "=r"(r[3]) : "r"(addr));
}
__device__ __forceinline__ void ldsm_x4_t(uint32_t* r, uint32_t addr) {
    asm volatile("ldmatrix.sync.aligned.m8n8.x4.trans.shared.b16 {%0,%1,%2,%3}, [%4];"
                 : "=r"(r[0]), "=r"(r[1]), "=r"(r[2]), "=r"(r[3]) : "r"(addr));
}
__device__ __forceinline__ void mma16816(float* c, const uint32_t* a, const uint32_t* b) {
    asm volatile("mma.sync.aligned.m16n8k16.row.col.f32.f16.f16.f32 "
                 "{%0,%1,%2,%3}, {%4,%5,%6,%7}, {%8,%9}, {%0,%1,%2,%3};"
                 : "+f"(c[0]), "+f"(c[1]), "+f"(c[2]), "+f"(c[3])
                 : "r"(a[0]), "r"(a[1]), "r"(a[2]), "r"(a[3]),
                   "r"(b[0]), "r"(b[1]));
}
#define CP16(s, g) asm volatile("cp.async.cg.shared.global [%0], [%1], 16;" :: "r"(s), "l"(g))
#define CP_COMMIT() asm volatile("cp.async.commit_group;" ::: "memory")
#define CP_WAIT(n)  asm volatile("cp.async.wait_group %0;" :: "n"(n) : "memory")

__device__ __forceinline__ float gelu_exact(float x) {
    return 0.5f * x * (1.0f + erff(x * 0.70710678118654752440f));
}

// ---------------------------------------------------------------------------
// Kernel 1 (prep): blocks 0..16383 -> hidden activations; rest -> W2 fp32->fp16
// ---------------------------------------------------------------------------
#define HID_BLOCKS 16384
#define W2H_BLOCKS ((KDIM * NGEMM) / (256 * 8))  // 8192
__global__ void prep_kernel(const float* __restrict__ vals,
                            const int* __restrict__ units,
                            const float* __restrict__ unit_emb,
                            const float* __restrict__ W1,
                            const float* __restrict__ b1,
                            const float* __restrict__ W2) {
    int b = blockIdx.x;
    if (b < HID_BLOCKS) {
        int i = b >> 2;
        float v = vals[i];
        int u = units[i];
        float e0 = unit_emb[u * 2];
        float e1 = unit_emb[u * 2 + 1];
        int k = ((b & 3) * 256 + threadIdx.x) * 8;
        __half2 h2[4];
        #pragma unroll
        for (int h = 0; h < 2; h++) {
            float4 w0 = *(const float4*)&W1[k + h * 4];
            float4 w1 = *(const float4*)&W1[KDIM + k + h * 4];
            float4 w2 = *(const float4*)&W1[2 * KDIM + k + h * 4];
            float4 bb = *(const float4*)&b1[k + h * 4];
            float r0 = gelu_exact(fmaf(v, w0.x, fmaf(e0, w1.x, fmaf(e1, w2.x, bb.x))));
            float r1 = gelu_exact(fmaf(v, w0.y, fmaf(e0, w1.y, fmaf(e1, w2.y, bb.y))));
            float r2 = gelu_exact(fmaf(v, w0.z, fmaf(e0, w1.z, fmaf(e1, w2.z, bb.z))));
            float r3 = gelu_exact(fmaf(v, w0.w, fmaf(e0, w1.w, fmaf(e1, w2.w, bb.w))));
            h2[h*2+0] = __floats2half2_rn(r0, r1);
            h2[h*2+1] = __floats2half2_rn(r2, r3);
        }
        *(uint4*)&g_hh[(size_t)i * KDIM + k] = *(uint4*)h2;
    } else {
        size_t idx = ((size_t)(b - HID_BLOCKS) * 256 + threadIdx.x) * 8;
        float4 a = *(const float4*)&W2[idx];
        float4 c = *(const float4*)&W2[idx + 4];
        __half2 h2[4];
        h2[0] = __floats2half2_rn(a.x, a.y);
        h2[1] = __floats2half2_rn(a.z, a.w);
        h2[2] = __floats2half2_rn(c.x, c.y);
        h2[3] = __floats2half2_rn(c.z, c.w);
        *(uint4*)&g_w2h[idx] = *(uint4*)h2;
    }
}

// ---------------------------------------------------------------------------
// Kernel 2 (fused): blocks 0..511 = GEMM 128x128x32, 4 warps @ 64x64, 5-stage;
// blocks 512.. = gather (8 tokens each, skipping numeric rows id>=FIN).
// GEMM epilogue writes numeric rows fully: new_emb[id-OLD] + acc + b2.
// ---------------------------------------------------------------------------
#define BM 128
#define BN 128
#define BK 32
#define NSTAGE 5
#define STG_B 16384
#define SMEM_TOTAL (NSTAGE * STG_B)
#define NIT (KDIM / BK)        // 256
#define GEMM_BLOCKS ((MGEMM / BM) * (NGEMM / BN))   // 512
#define TOK_PER_BLK 8
#define GATHER_BLOCKS (T_TOK / TOK_PER_BLK)         // 4096

__global__ __launch_bounds__(128, 2)
void fused_kernel(const int* __restrict__ ids,
                  const float* __restrict__ orig_emb,
                  const float* __restrict__ new_emb,
                  const float* __restrict__ b2,
                  const int* __restrict__ pos,
                  float* __restrict__ out) {
    if (blockIdx.x >= GEMM_BLOCKS) {
        // ----- gather part (128 threads, 4 float4 per row each) -----
        const int tbase = (blockIdx.x - GEMM_BLOCKS) * TOK_PER_BLK;
        const int i = threadIdx.x;
        #pragma unroll
        for (int tk = 0; tk < TOK_PER_BLK; tk++) {
            const int t = tbase + tk;
            const int id = ids[t];
            if (id >= FINV) continue;            // numeric rows written by GEMM
            const float4* src = (id >= OLDV)
                ? (const float4*)(new_emb + (size_t)(id - OLDV) * EMB_D)
                : (const float4*)(orig_emb + (size_t)id * EMB_D);
            float4* dst = (float4*)(out + (size_t)t * EMB_D);
            dst[i]       = src[i];
            dst[i + 128] = src[i + 128];
            dst[i + 256] = src[i + 256];
            dst[i + 384] = src[i + 384];
        }
        return;
    }

    // ----- GEMM part -----
    extern __shared__ char smem[];
    const uint32_t sbase = s2u(smem);
    const int tid = threadIdx.x;
    const int lane = tid & 31;
    const int wid = tid >> 5;          // 0..3
    const int warp_m = wid >> 1;       // 0..1 (64 rows each)
    const int warp_n = wid & 1;        // 0..1 (64 cols each)
    const int m0 = (blockIdx.x >> 4) * BM;
    const int n0 = (blockIdx.x & 15) * BN;

    const __half* Ag = g_hh + (size_t)m0 * KDIM;
    const __half* Bg = g_w2h + n0;

    // cp.async mapping (128 threads):
    // A: 128 rows x 64B; thread t -> row t, 4 chunks (swizzle c ^ ((t>>1)&3))
    // B: 32 rows x 256B; thread t -> row t>>2, chunks (t&3)*4+j (swz ^(bk&7))
    const int bk = tid >> 2;
    const int bc0 = (tid & 3) * 4;
    uint32_t a_sm[4], b_sm[4];
    #pragma unroll
    for (int j = 0; j < 4; j++) {
        a_sm[j] = sbase + tid * 64 + (((j) ^ ((tid >> 1) & 3)) * 16);
        b_sm[j] = sbase + 8192 + bk * 256 + (((bc0 + j) ^ (bk & 7)) * 16);
    }
    const __half* agp = Ag + (size_t)tid * KDIM;
    const __half* bgp0 = Bg + (size_t)bk * NGEMM + bc0 * 8;

    // prologue: stages 0..3
    #pragma unroll
    for (int s = 0; s < NSTAGE - 1; s++) {
        const uint32_t so = s * STG_B;
        const __half* ag = agp + s * BK;
        const __half* bg = bgp0 + (size_t)(s * BK) * NGEMM;
        #pragma unroll
        for (int j = 0; j < 4; j++) {
            CP16(a_sm[j] + so, ag + j * 8);
            CP16(b_sm[j] + so, bg + j * 8);
        }
        CP_COMMIT();
    }

    float acc[4][8][4];
    #pragma unroll
    for (int mt = 0; mt < 4; mt++)
        #pragma unroll
        for (int nt = 0; nt < 8; nt++)
            #pragma unroll
            for (int j = 0; j < 4; j++) acc[mt][nt][j] = 0.0f;

    // fragment smem offsets (relative to stage base)
    uint32_t a_off[2][4], b_off[2][4];
    #pragma unroll
    for (int ks = 0; ks < 2; ks++) {
        #pragma unroll
        for (int mt = 0; mt < 4; mt++) {
            int row = warp_m * 64 + mt * 16 + (lane & 15);
            int ch = ks * 2 + (lane >> 4);
            a_off[ks][mt] = row * 64 + ((ch ^ ((row >> 1) & 3)) * 16);
        }
        #pragma unroll
        for (int np = 0; np < 4; np++) {
            int k = ks * 16 + (lane & 15);
            int ch = warp_n * 8 + np * 2 + (lane >> 4);
            b_off[ks][np] = 8192 + k * 256 + ((ch ^ (k & 7)) * 16);
        }
    }

    int rd = 0, wr = NSTAGE - 1;

    #pragma unroll 1
    for (int kt = 0; kt < NIT; kt++) {
        CP_WAIT(NSTAGE - 2);
        __syncthreads();

        if (kt + NSTAGE - 1 < NIT) {
            const int s = kt + NSTAGE - 1;
            const uint32_t so = wr * STG_B;
            const __half* ag = agp + s * BK;
            const __half* bg = bgp0 + (size_t)(s * BK) * NGEMM;
            #pragma unroll
            for (int j = 0; j < 4; j++) {
                CP16(a_sm[j] + so, ag + j * 8);
                CP16(b_sm[j] + so, bg + j * 8);
            }
        }
        CP_COMMIT();

        const uint32_t st = sbase + rd * STG_B;
        #pragma unroll
        for (int ks = 0; ks < 2; ks++) {
            uint32_t a[4][4], b[4][4];
            #pragma unroll
            for (int mt = 0; mt < 4; mt++) ldsm_x4(a[mt], st + a_off[ks][mt]);
            #pragma unroll
            for (int np = 0; np < 4; np++) ldsm_x4_t(b[np], st + b_off[ks][np]);
            #pragma unroll
            for (int mt = 0; mt < 4; mt++) {
                #pragma unroll
                for (int np = 0; np < 4; np++) {
                    mma16816(acc[mt][np * 2],     a[mt], &b[np][0]);
                    mma16816(acc[mt][np * 2 + 1], a[mt], &b[np][2]);
                }
            }
        }
        rd = (rd == NSTAGE - 1) ? 0 : rd + 1;
        wr = (wr == NSTAGE - 1) ? 0 : wr + 1;
    }

    // epilogue: numeric rows written in full (no dependence on gather):
    // out[p, c] = new_emb[id(p)-OLDV, c] + acc + b2[c]
    #pragma unroll
    for (int mt = 0; mt < 4; mt++) {
        const int rbase = m0 + warp_m * 64 + mt * 16 + (lane >> 2);
        const int p0 = pos[rbase];
        const int p1 = pos[rbase + 8];
        const int cbase = n0 + warp_n * 64 + (lane & 3) * 2;
        const float* ne0 = new_emb + (size_t)(ids[p0] - OLDV) * EMB_D + cbase;
        const float* ne1 = new_emb + (size_t)(ids[p1] - OLDV) * EMB_D + cbase;
        float* o0 = out + (size_t)p0 * EMB_D + cbase;
        float* o1 = out + (size_t)p1 * EMB_D + cbase;
        const float* bb = b2 + cbase;
        #pragma unroll
        for (int nt = 0; nt < 8; nt++) {
            float bx = bb[nt * 8], by = bb[nt * 8 + 1];
            float2 e0 = *(const float2*)(ne0 + nt * 8);
            float2 v0;
            v0.x = e0.x + acc[mt][nt][0] + bx;
            v0.y = e0.y + acc[mt][nt][1] + by;
            *(float2*)(o0 + nt * 8) = v0;
            float2 e1 = *(const float2*)(ne1 + nt * 8);
            float2 v1;
            v1.x = e1.x + acc[mt][nt][2] + bx;
            v1.y = e1.y + acc[mt][nt][3] + by;
            *(float2*)(o1 + nt * 8) = v1;
        }
    }
}

// ---------------------------------------------------------------------------
extern "C" void kernel_launch(void* const* d_in, const int* in_sizes, int n_in,
                              void* d_out, int out_size) {
    const int*   input_ids  = (const int*)d_in[0];
    const int*   num_pos    = (const int*)d_in[1];
    const float* num_values = (const float*)d_in[2];
    const int*   num_units  = (const int*)d_in[3];
    const float* orig_emb   = (const float*)d_in[4];
    const float* new_emb    = (const float*)d_in[5];
    const float* unit_emb   = (const float*)d_in[6];
    const float* W1         = (const float*)d_in[7];
    const float* b1         = (const float*)d_in[8];
    const float* W2         = (const float*)d_in[9];
    const float* b2         = (const float*)d_in[10];
    float* out = (float*)d_out;

    cudaFuncSetAttribute(fused_kernel,
                         cudaFuncAttributeMaxDynamicSharedMemorySize, SMEM_TOTAL);

    // 1) hidden activations + W2 conversion (one launch)
    prep_kernel<<<HID_BLOCKS + W2H_BLOCKS, 256>>>(num_values, num_units, unit_emb,
                                                  W1, b1, W2);

    // 2) fused GEMM + gather (gather backfills GEMM tail wave)
    fused_kernel<<<GEMM_BLOCKS + GATHER_BLOCKS, 128, SMEM_TOTAL>>>(
        input_ids, orig_emb, new_emb, b2, num_pos, out);
}

// round 12
// speedup vs baseline: 1.7558x; 1.7558x over previous
#include <cuda_runtime.h>
#include <cuda_fp16.h>
#include <math.h>
#include <stdint.h>

#define OLDV 50257
#define FINV 52257
#define EMB_D 2048
#define T_TOK 32768
#define NNUM 4096
#define KDIM 8192
#define MGEMM 4096
#define NGEMM 2048

// fp16 scratch: hidden activations and W2
__device__ __align__(128) __half g_hh[(size_t)NNUM * KDIM];    // [4096, 8192] row-major
__device__ __align__(128) __half g_w2h[(size_t)KDIM * NGEMM];  // [8192, 2048] row-major

// ---------------------------------------------------------------------------
// helpers
// ---------------------------------------------------------------------------
__device__ __forceinline__ uint32_t s2u(const void* p) {
    uint32_t a;
    asm("{ .reg .u64 t; cvta.to.shared.u64 t, %1; cvt.u32.u64 %0, t; }"
        : "=r"(a) : "l"(p));
    return a;
}
__device__ __forceinline__ void ldsm_x4(uint32_t* r, uint32_t addr) {
    asm volatile("ldmatrix.sync.aligned.m8n8.x4.shared.b16 {%0,%1,%2,%3}, [%4];"
                 : "=r"(r[0]), "=r"(r[1]), "=r"(r[2]), "=r"(r[3]) : "r"(addr));
}
__device__ __forceinline__ void ldsm_x4_t(uint32_t* r, uint32_t addr) {
    asm volatile("ldmatrix.sync.aligned.m8n8.x4.trans.shared.b16 {%0,%1,%2,%3}, [%4];"
                 : "=r"(r[0]), "=r"(r[1]), "=r"(r[2]), "=r"(r[3]) : "r"(addr));
}
__device__ __forceinline__ void mma16816(float* c, const uint32_t* a, const uint32_t* b) {
    asm volatile("mma.sync.aligned.m16n8k16.row.col.f32.f16.f16.f32 "
                 "{%0,%1,%2,%3}, {%4,%5,%6,%7}, {%8,%9}, {%0,%1,%2,%3};"
                 : "+f"(c[0]), "+f"(c[1]), "+f"(c[2]), "+f"(c[3])
                 : "r"(a[0]), "r"(a[1]), "r"(a[2]), "r"(a[3]),
                   "r"(b[0]), "r"(b[1]));
}
#define CP16(s, g) asm volatile("cp.async.cg.shared.global [%0], [%1], 16;" :: "r"(s), "l"(g))
#define CP_COMMIT() asm volatile("cp.async.commit_group;" ::: "memory")
#define CP_WAIT(n)  asm volatile("cp.async.wait_group %0;" :: "n"(n) : "memory")

__device__ __forceinline__ float gelu_exact(float x) {
    return 0.5f * x * (1.0f + erff(x * 0.70710678118654752440f));
}

// ---------------------------------------------------------------------------
// Kernel 1 (prep):
//  blocks 0..2047: hidden activations, 8 tokens per block, W1 held in regs.
//  blocks 2048.. : W2 fp32 -> fp16 conversion.
// ---------------------------------------------------------------------------
#define TOKS_PER_HB 8
#define HID_BLOCKS ((KDIM / (256 * 8)) * (NNUM / TOKS_PER_HB))   // 4 * 512 = 2048
#define W2H_BLOCKS ((KDIM * NGEMM) / (256 * 8))                  // 8192
__global__ void prep_kernel(const float* __restrict__ vals,
                            const int* __restrict__ units,
                            const float* __restrict__ unit_emb,
                            const float* __restrict__ W1,
                            const float* __restrict__ b1,
                            const float* __restrict__ W2) {
    int b = blockIdx.x;
    if (b < HID_BLOCKS) {
        const int kb = b & 3;                  // k-chunk 0..3
        const int i0 = (b >> 2) * TOKS_PER_HB; // first token
        const int k = (kb * 256 + threadIdx.x) * 8;
        // load W1 rows + b1 once into registers (32 floats)
        float4 w0a = *(const float4*)&W1[k],            w0b = *(const float4*)&W1[k + 4];
        float4 w1a = *(const float4*)&W1[KDIM + k],     w1b = *(const float4*)&W1[KDIM + k + 4];
        float4 w2a = *(const float4*)&W1[2*KDIM + k],   w2b = *(const float4*)&W1[2*KDIM + k + 4];
        float4 bba = *(const float4*)&b1[k],            bbb = *(const float4*)&b1[k + 4];
        #pragma unroll
        for (int t = 0; t < TOKS_PER_HB; t++) {
            const int i = i0 + t;
            const float v = vals[i];
            const int u = units[i];
            const float e0 = unit_emb[u * 2];
            const float e1 = unit_emb[u * 2 + 1];
            __half2 h2[4];
            {
                float r0 = gelu_exact(fmaf(v, w0a.x, fmaf(e0, w1a.x, fmaf(e1, w2a.x, bba.x))));
                float r1 = gelu_exact(fmaf(v, w0a.y, fmaf(e0, w1a.y, fmaf(e1, w2a.y, bba.y))));
                float r2 = gelu_exact(fmaf(v, w0a.z, fmaf(e0, w1a.z, fmaf(e1, w2a.z, bba.z))));
                float r3 = gelu_exact(fmaf(v, w0a.w, fmaf(e0, w1a.w, fmaf(e1, w2a.w, bba.w))));
                h2[0] = __floats2half2_rn(r0, r1);
                h2[1] = __floats2half2_rn(r2, r3);
            }
            {
                float r0 = gelu_exact(fmaf(v, w0b.x, fmaf(e0, w1b.x, fmaf(e1, w2b.x, bbb.x))));
                float r1 = gelu_exact(fmaf(v, w0b.y, fmaf(e0, w1b.y, fmaf(e1, w2b.y, bbb.y))));
                float r2 = gelu_exact(fmaf(v, w0b.z, fmaf(e0, w1b.z, fmaf(e1, w2b.z, bbb.z))));
                float r3 = gelu_exact(fmaf(v, w0b.w, fmaf(e0, w1b.w, fmaf(e1, w2b.w, bbb.w))));
                h2[2] = __floats2half2_rn(r0, r1);
                h2[3] = __floats2half2_rn(r2, r3);
            }
            *(uint4*)&g_hh[(size_t)i * KDIM + k] = *(uint4*)h2;
        }
    } else {
        size_t idx = ((size_t)(b - HID_BLOCKS) * 256 + threadIdx.x) * 8;
        float4 a = *(const float4*)&W2[idx];
        float4 c = *(const float4*)&W2[idx + 4];
        __half2 h2[4];
        h2[0] = __floats2half2_rn(a.x, a.y);
        h2[1] = __floats2half2_rn(a.z, a.w);
        h2[2] = __floats2half2_rn(c.x, c.y);
        h2[3] = __floats2half2_rn(c.z, c.w);
        *(uint4*)&g_w2h[idx] = *(uint4*)h2;
    }
}

// ---------------------------------------------------------------------------
// Kernel 2 (fused): blocks 0..511 = fp16 mma.sync GEMM (R9 config);
// blocks 512.. = gather (8 tokens each, SKIPPING numeric rows id>=FIN).
// GEMM epilogue writes numeric rows fully: new_emb[id-OLD] + acc + b2.
// ---------------------------------------------------------------------------
#define BM 128
#define BN 128
#define BK 32
#define NSTAGE 4
#define STG_B 16384
#define SMEM_TOTAL (NSTAGE * STG_B)
#define NIT (KDIM / BK)        // 256
#define GEMM_BLOCKS ((MGEMM / BM) * (NGEMM / BN))   // 512
#define TOK_PER_BLK 8
#define GATHER_BLOCKS (T_TOK / TOK_PER_BLK)         // 4096

__global__ __launch_bounds__(256, 2)
void fused_kernel(const int* __restrict__ ids,
                  const float* __restrict__ orig_emb,
                  const float* __restrict__ new_emb,
                  const float* __restrict__ b2,
                  const int* __restrict__ pos,
                  float* __restrict__ out) {
    if (blockIdx.x >= GEMM_BLOCKS) {
        // ----- gather part -----
        const int tbase = (blockIdx.x - GEMM_BLOCKS) * TOK_PER_BLK;
        const int i = threadIdx.x;
        #pragma unroll
        for (int tk = 0; tk < TOK_PER_BLK; tk++) {
            const int t = tbase + tk;
            const int id = ids[t];
            if (id >= FINV) continue;            // numeric rows written by GEMM
            const float4* src = (id >= OLDV)
                ? (const float4*)(new_emb + (size_t)(id - OLDV) * EMB_D)
                : (const float4*)(orig_emb + (size_t)id * EMB_D);
            float4* dst = (float4*)(out + (size_t)t * EMB_D);
            dst[i]       = src[i];
            dst[i + 256] = src[i + 256];
        }
        return;
    }

    // ----- GEMM part (R9 mainloop) -----
    extern __shared__ char smem[];
    const uint32_t sbase = s2u(smem);
    const int tid = threadIdx.x;
    const int lane = tid & 31;
    const int wid = tid >> 5;
    const int warp_m = wid >> 1;
    const int warp_n = wid & 1;
    const int m0 = (blockIdx.x >> 4) * BM;
    const int n0 = (blockIdx.x & 15) * BN;

    const __half* Ag = g_hh + (size_t)m0 * KDIM;
    const __half* Bg = g_w2h + n0;

    const int ar = tid >> 1;
    const int ac0 = (tid & 1) * 2;
    const int bk = tid >> 3;
    const int bc0 = (tid & 7) * 2;
    const uint32_t a_s0 = sbase + ar * 64 + (((ac0)     ^ ((ar >> 1) & 3)) * 16);
    const uint32_t a_s1 = sbase + ar * 64 + (((ac0 + 1) ^ ((ar >> 1) & 3)) * 16);
    const uint32_t b_s0 = sbase + 8192 + bk * 256 + (((bc0)     ^ (bk & 7)) * 16);
    const uint32_t b_s1 = sbase + 8192 + bk * 256 + (((bc0 + 1) ^ (bk & 7)) * 16);
    const __half* agp = Ag + (size_t)ar * KDIM;

    #pragma unroll
    for (int s = 0; s < NSTAGE - 1; s++) {
        const uint32_t so = s * STG_B;
        CP16(a_s0 + so, agp + s * BK + ac0 * 8);
        CP16(a_s1 + so, agp + s * BK + (ac0 + 1) * 8);
        const __half* bgp = Bg + (size_t)(s * BK + bk) * NGEMM;
        CP16(b_s0 + so, bgp + bc0 * 8);
        CP16(b_s1 + so, bgp + (bc0 + 1) * 8);
        CP_COMMIT();
    }

    float acc[2][8][4];
    #pragma unroll
    for (int mt = 0; mt < 2; mt++)
        #pragma unroll
        for (int nt = 0; nt < 8; nt++)
            #pragma unroll
            for (int j = 0; j < 4; j++) acc[mt][nt][j] = 0.0f;

    uint32_t a_off[2][2], b_off[2][4];
    #pragma unroll
    for (int ks = 0; ks < 2; ks++) {
        #pragma unroll
        for (int mt = 0; mt < 2; mt++) {
            int row = warp_m * 32 + mt * 16 + (lane & 15);
            int ch = ks * 2 + (lane >> 4);
            a_off[ks][mt] = row * 64 + ((ch ^ ((row >> 1) & 3)) * 16);
        }
        #pragma unroll
        for (int np = 0; np < 4; np++) {
            int k = ks * 16 + (lane & 15);
            int ch = warp_n * 8 + np * 2 + (lane >> 4);
            b_off[ks][np] = 8192 + k * 256 + ((ch ^ (k & 7)) * 16);
        }
    }

    #pragma unroll 1
    for (int kt = 0; kt < NIT; kt++) {
        CP_WAIT(NSTAGE - 2);
        __syncthreads();

        if (kt + NSTAGE - 1 < NIT) {
            const int s = kt + NSTAGE - 1;
            const uint32_t so = (s & 3) * STG_B;
            CP16(a_s0 + so, agp + s * BK + ac0 * 8);
            CP16(a_s1 + so, agp + s * BK + (ac0 + 1) * 8);
            const __half* bgp = Bg + (size_t)(s * BK + bk) * NGEMM;
            CP16(b_s0 + so, bgp + bc0 * 8);
            CP16(b_s1 + so, bgp + (bc0 + 1) * 8);
        }
        CP_COMMIT();

        const uint32_t st = sbase + (kt & 3) * STG_B;
        #pragma unroll
        for (int ks = 0; ks < 2; ks++) {
            uint32_t a[2][4], b[4][4];
            #pragma unroll
            for (int mt = 0; mt < 2; mt++) ldsm_x4(a[mt], st + a_off[ks][mt]);
            #pragma unroll
            for (int np = 0; np < 4; np++) ldsm_x4_t(b[np], st + b_off[ks][np]);
            #pragma unroll
            for (int mt = 0; mt < 2; mt++) {
                #pragma unroll
                for (int np = 0; np < 4; np++) {
                    mma16816(acc[mt][np * 2],     a[mt], &b[np][0]);
                    mma16816(acc[mt][np * 2 + 1], a[mt], &b[np][2]);
                }
            }
        }
    }

    // epilogue: numeric rows written in full (no dependence on gather):
    // out[p, c] = new_emb[id(p)-OLDV, c] + acc + b2[c]
    #pragma unroll
    for (int mt = 0; mt < 2; mt++) {
        const int rbase = m0 + warp_m * 32 + mt * 16 + (lane >> 2);
        const int p0 = pos[rbase];
        const int p1 = pos[rbase + 8];
        const int cbase = n0 + warp_n * 64 + (lane & 3) * 2;
        const float* ne0 = new_emb + (size_t)(ids[p0] - OLDV) * EMB_D + cbase;
        const float* ne1 = new_emb + (size_t)(ids[p1] - OLDV) * EMB_D + cbase;
        float* o0 = out + (size_t)p0 * EMB_D + cbase;
        float* o1 = out + (size_t)p1 * EMB_D + cbase;
        const float* bb = b2 + cbase;
        #pragma unroll
        for (int nt = 0; nt < 8; nt++) {
            float bx = bb[nt * 8], by = bb[nt * 8 + 1];
            float2 e0 = *(const float2*)(ne0 + nt * 8);
            float2 v0;
            v0.x = e0.x + acc[mt][nt][0] + bx;
            v0.y = e0.y + acc[mt][nt][1] + by;
            *(float2*)(o0 + nt * 8) = v0;
            float2 e1 = *(const float2*)(ne1 + nt * 8);
            float2 v1;
            v1.x = e1.x + acc[mt][nt][2] + bx;
            v1.y = e1.y + acc[mt][nt][3] + by;
            *(float2*)(o1 + nt * 8) = v1;
        }
    }
}

// ---------------------------------------------------------------------------
extern "C" void kernel_launch(void* const* d_in, const int* in_sizes, int n_in,
                              void* d_out, int out_size) {
    const int*   input_ids  = (const int*)d_in[0];
    const int*   num_pos    = (const int*)d_in[1];
    const float* num_values = (const float*)d_in[2];
    const int*   num_units  = (const int*)d_in[3];
    const float* orig_emb   = (const float*)d_in[4];
    const float* new_emb    = (const float*)d_in[5];
    const float* unit_emb   = (const float*)d_in[6];
    const float* W1         = (const float*)d_in[7];
    const float* b1         = (const float*)d_in[8];
    const float* W2         = (const float*)d_in[9];
    const float* b2         = (const float*)d_in[10];
    float* out = (float*)d_out;

    cudaFuncSetAttribute(fused_kernel,
                         cudaFuncAttributeMaxDynamicSharedMemorySize, SMEM_TOTAL);

    // 1) hidden activations (W1 reused across 8 tokens) + W2 conversion
    prep_kernel<<<HID_BLOCKS + W2H_BLOCKS, 256>>>(num_values, num_units, unit_emb,
                                                  W1, b1, W2);

    // 2) fused GEMM + gather (gather backfills GEMM tail wave)
    fused_kernel<<<GEMM_BLOCKS + GATHER_BLOCKS, 256, SMEM_TOTAL>>>(
        input_ids, orig_emb, new_emb, b2, num_pos, out);
}